// round 10
// baseline (speedup 1.0000x reference)
#include <cuda_runtime.h>
#include <cuda_fp16.h>
#include <math.h>
#include <stdint.h>

#define N_NODES 50000
#define N_EDGES 800000
#define F0 128
#define F1 96
#define F2 96
#define F3 40
#define NBLK 74
#define CSR_THREADS 1024
#define CHUNK ((N_NODES + NBLK - 1) / NBLK)   // 676
#define HALF_A 25152                          // 131 gemm blocks * 192 rows

// ---------------- scratch (static device globals; no allocation) ----------------
__device__ int    g_deg[N_NODES];
__device__ int    g_cur[N_NODES];
__device__ int    g_off[N_NODES + 1];
__device__ int    g_csr[N_EDGES];
__device__ int    g_bsum[NBLK];
__device__ int    g_barrier_ctr;
__device__ int    g_done_ctr;
__device__ __half g_t1[(size_t)N_NODES * F1];
__device__ float  g_h1[(size_t)N_NODES * F1];
__device__ __half g_t2[(size_t)N_NODES * F2];
__device__ float  g_h2[(size_t)N_NODES * F2];
__device__ __half g_t3[(size_t)N_NODES * F3];

// ---------------- edge index access ----------------
__device__ __forceinline__ int edge_src(const int* ei, int e, int is64) {
    return is64 ? ei[2 * e] : ei[e];
}
__device__ __forceinline__ int edge_dst(const int* ei, int e, int is64) {
    return is64 ? ei[2 * (N_EDGES + e)] : ei[N_EDGES + e];
}

// ---------------- software grid barrier (74 co-resident blocks) ----------------
__device__ __forceinline__ void grid_barrier(int phase) {
    __syncthreads();
    if (threadIdx.x == 0) {
        __threadfence();
        atomicAdd(&g_barrier_ctr, 1);
        int target = phase * NBLK;
        while ((*(volatile int*)&g_barrier_ctr) - target < 0)
            __nanosleep(64);
    }
    __syncthreads();
    __threadfence();
}

// ---------------- single persistent CSR-build kernel ----------------
__global__ void __launch_bounds__(CSR_THREADS) csr_build_kernel(const int* __restrict__ ei) {
    __shared__ int s_is64;
    __shared__ int s_boff;
    __shared__ int wsum[32];

    int tid  = threadIdx.x;
    int lane = tid & 31, w = tid >> 5;
    int gtid = blockIdx.x * CSR_THREADS + tid;
    constexpr int NT = NBLK * CSR_THREADS;

    if (tid < 32) {
        int acc = 0;
#pragma unroll
        for (int j = 0; j < 4; j++) acc |= ei[1 + 2 * (tid * 4 + j)];
#pragma unroll
        for (int o = 16; o > 0; o >>= 1) acc |= __shfl_xor_sync(0xffffffffu, acc, o);
        if (tid == 0) s_is64 = (acc == 0) ? 1 : 0;
    }
    __syncthreads();
    int is64 = s_is64;

    for (int i = gtid; i < N_NODES; i += NT) g_deg[i] = 0;
    grid_barrier(1);

    for (int e = gtid; e < N_EDGES; e += NT)
        atomicAdd(&g_deg[edge_dst(ei, e, is64)], 1);
    grid_barrier(2);

    int cbase = blockIdx.x * CHUNK;
    int i0 = cbase + tid;
    int v = (tid < CHUNK && i0 < N_NODES) ? g_deg[i0] : 0;
    {
        int s = v;
#pragma unroll
        for (int o = 16; o > 0; o >>= 1) s += __shfl_xor_sync(0xffffffffu, s, o);
        if (lane == 0) wsum[w] = s;
        __syncthreads();
        if (w == 0) {
            int t = wsum[lane];
#pragma unroll
            for (int o = 16; o > 0; o >>= 1) t += __shfl_xor_sync(0xffffffffu, t, o);
            if (lane == 0) g_bsum[blockIdx.x] = t;
        }
    }
    grid_barrier(3);

    if (tid == 0) {
        int s = 0;
        for (int b = 0; b < (int)blockIdx.x; b++) s += g_bsum[b];
        s_boff = s;
    }
    __syncthreads();
    {
        int incl = v;
#pragma unroll
        for (int o = 1; o < 32; o <<= 1) {
            int u = __shfl_up_sync(0xffffffffu, incl, o);
            if (lane >= o) incl += u;
        }
        if (lane == 31) wsum[w] = incl;
        __syncthreads();
        if (w == 0) {
            int s = wsum[lane];
#pragma unroll
            for (int o = 1; o < 32; o <<= 1) {
                int u = __shfl_up_sync(0xffffffffu, s, o);
                if (lane >= o) s += u;
            }
            wsum[lane] = s;
        }
        __syncthreads();
        incl += ((w > 0) ? wsum[w - 1] : 0) + s_boff;
        if (tid < CHUNK && i0 < N_NODES) {
            g_off[i0 + 1] = incl;
            g_cur[i0]     = incl - v;
        }
        if (blockIdx.x == 0 && tid == 0) g_off[0] = 0;
    }
    grid_barrier(4);

    for (int e = gtid; e < N_EDGES; e += NT) {
        int d = edge_dst(ei, e, is64);
        int s = edge_src(ei, e, is64);
        int p = atomicAdd(&g_cur[d], 1);
        g_csr[p] = s;
    }

    __syncthreads();
    if (tid == 0) {
        __threadfence();
        int d = atomicAdd(&g_done_ctr, 1);
        if (d == NBLK - 1) {
            g_barrier_ctr = 0;
            g_done_ctr = 0;
            __threadfence();
        }
    }
}

// ---------------- 3xTF32 tensor-core GEMM, 32 rows/warp, row range [base, limit) ----------------
__device__ __forceinline__ uint32_t f2tf32(float f) {
    uint32_t r;
    asm("cvt.rna.tf32.f32 %0, %1;" : "=r"(r) : "f"(f));
    return r;
}

__device__ __forceinline__ void mma8(float c[4], const uint32_t a[4],
                                     uint32_t b0, uint32_t b1) {
    asm volatile(
        "mma.sync.aligned.m16n8k8.row.col.f32.tf32.tf32.f32 "
        "{%0,%1,%2,%3}, {%4,%5,%6,%7}, {%8,%9}, {%0,%1,%2,%3};"
        : "+f"(c[0]), "+f"(c[1]), "+f"(c[2]), "+f"(c[3])
        : "r"(a[0]), "r"(a[1]), "r"(a[2]), "r"(a[3]), "r"(b0), "r"(b1));
}

template <int K, int N>
__global__ void __launch_bounds__(192, 2) mma_gemm_kernel(
        const float* __restrict__ X, const float* __restrict__ W,
        __half* __restrict__ Y, int base, int limit) {
    constexpr int NT  = N / 8;
    constexpr int PAD = (8 - (N % 32) + 32) % 32;
    constexpr int PS  = N + PAD;
    extern __shared__ uint32_t smem[];
    uint32_t* sHi = smem;
    uint32_t* sLo = smem + K * PS;

    int tid = threadIdx.x;
    for (int i = tid; i < K * N; i += 192) {
        int k = i / N, n = i % N;
        float w = __ldg(W + i);
        uint32_t hi = f2tf32(w);
        sHi[k * PS + n] = hi;
        sLo[k * PS + n] = f2tf32(w - __uint_as_float(hi));
    }
    __syncthreads();

    int warp = tid >> 5, lane = tid & 31;
    int tig = lane & 3, grp = lane >> 2;
    int row0 = base + blockIdx.x * 192 + warp * 32;
    int r0 = row0 + grp,      r1 = row0 + grp + 8;
    int r2 = row0 + grp + 16, r3 = row0 + grp + 24;
    const float* xr0 = X + (size_t)((r0 < limit) ? r0 : (limit - 1)) * K;
    const float* xr1 = X + (size_t)((r1 < limit) ? r1 : (limit - 1)) * K;
    const float* xr2 = X + (size_t)((r2 < limit) ? r2 : (limit - 1)) * K;
    const float* xr3 = X + (size_t)((r3 < limit) ? r3 : (limit - 1)) * K;

    float c0[NT][4], c1[NT][4];
#pragma unroll
    for (int nt = 0; nt < NT; nt++)
#pragma unroll
        for (int j = 0; j < 4; j++) { c0[nt][j] = 0.f; c1[nt][j] = 0.f; }

#pragma unroll 1
    for (int k0 = 0; k0 < K; k0 += 8) {
        float a0 = __ldg(xr0 + k0 + tig);
        float a1 = __ldg(xr1 + k0 + tig);
        float a2 = __ldg(xr0 + k0 + tig + 4);
        float a3 = __ldg(xr1 + k0 + tig + 4);
        float a4 = __ldg(xr2 + k0 + tig);
        float a5 = __ldg(xr3 + k0 + tig);
        float a6 = __ldg(xr2 + k0 + tig + 4);
        float a7 = __ldg(xr3 + k0 + tig + 4);
        uint32_t ahi0[4] = {f2tf32(a0), f2tf32(a1), f2tf32(a2), f2tf32(a3)};
        uint32_t alo0[4] = {f2tf32(a0 - __uint_as_float(ahi0[0])),
                            f2tf32(a1 - __uint_as_float(ahi0[1])),
                            f2tf32(a2 - __uint_as_float(ahi0[2])),
                            f2tf32(a3 - __uint_as_float(ahi0[3]))};
        uint32_t ahi1[4] = {f2tf32(a4), f2tf32(a5), f2tf32(a6), f2tf32(a7)};
        uint32_t alo1[4] = {f2tf32(a4 - __uint_as_float(ahi1[0])),
                            f2tf32(a5 - __uint_as_float(ahi1[1])),
                            f2tf32(a6 - __uint_as_float(ahi1[2])),
                            f2tf32(a7 - __uint_as_float(ahi1[3]))};
        const uint32_t* rHi0 = sHi + (k0 + tig) * PS + grp;
        const uint32_t* rHi1 = sHi + (k0 + tig + 4) * PS + grp;
        const uint32_t* rLo0 = sLo + (k0 + tig) * PS + grp;
        const uint32_t* rLo1 = sLo + (k0 + tig + 4) * PS + grp;
#pragma unroll
        for (int nt = 0; nt < NT; nt++) {
            uint32_t b0h = rHi0[nt * 8], b1h = rHi1[nt * 8];
            uint32_t b0l = rLo0[nt * 8], b1l = rLo1[nt * 8];
            mma8(c0[nt], ahi0, b0h, b1h);
            mma8(c0[nt], alo0, b0h, b1h);
            mma8(c0[nt], ahi0, b0l, b1l);
            mma8(c1[nt], ahi1, b0h, b1h);
            mma8(c1[nt], alo1, b0h, b1h);
            mma8(c1[nt], ahi1, b0l, b1l);
        }
    }

#pragma unroll
    for (int nt = 0; nt < NT; nt++) {
        int col = nt * 8 + 2 * tig;
        if (r0 < limit)
            *(__half2*)(Y + (size_t)r0 * N + col) = __floats2half2_rn(c0[nt][0], c0[nt][1]);
        if (r1 < limit)
            *(__half2*)(Y + (size_t)r1 * N + col) = __floats2half2_rn(c0[nt][2], c0[nt][3]);
        if (r2 < limit)
            *(__half2*)(Y + (size_t)r2 * N + col) = __floats2half2_rn(c1[nt][0], c1[nt][1]);
        if (r3 < limit)
            *(__half2*)(Y + (size_t)r3 * N + col) = __floats2half2_rn(c1[nt][2], c1[nt][3]);
    }
}

// ---------------- gather aggregation (fp16 in, fp32 accum) + fused epilogue ----------------
__device__ __forceinline__ void acc_h4(float4& acc, uint2 v) {
    float2 f0 = __half22float2(*reinterpret_cast<__half2*>(&v.x));
    float2 f1 = __half22float2(*reinterpret_cast<__half2*>(&v.y));
    acc.x += f0.x; acc.y += f0.y; acc.z += f1.x; acc.w += f1.y;
}

template <int D, int EPI>
__global__ void agg_kernel(const __half* __restrict__ xin, const float* __restrict__ bias,
                           float* __restrict__ xout, int base, int limit) {
    int gw   = base + ((blockIdx.x * blockDim.x + threadIdx.x) >> 5);
    int lane = threadIdx.x & 31;
    if (gw >= limit) return;
    constexpr int D4 = D / 4;
    float4 acc = make_float4(0.f, 0.f, 0.f, 0.f);
    int beg = g_off[gw], end = g_off[gw + 1];
    int e = beg;
    for (; e + 3 < end; e += 4) {
        int s0 = g_csr[e], s1 = g_csr[e + 1], s2 = g_csr[e + 2], s3 = g_csr[e + 3];
        if (lane < D4) {
            uint2 v0 = __ldg((const uint2*)(xin + (size_t)s0 * D) + lane);
            uint2 v1 = __ldg((const uint2*)(xin + (size_t)s1 * D) + lane);
            uint2 v2 = __ldg((const uint2*)(xin + (size_t)s2 * D) + lane);
            uint2 v3 = __ldg((const uint2*)(xin + (size_t)s3 * D) + lane);
            acc_h4(acc, v0);
            acc_h4(acc, v1);
            acc_h4(acc, v2);
            acc_h4(acc, v3);
        }
    }
    for (; e < end; e++) {
        int s0 = g_csr[e];
        if (lane < D4) {
            uint2 v = __ldg((const uint2*)(xin + (size_t)s0 * D) + lane);
            acc_h4(acc, v);
        }
    }
    float4 bb = (lane < D4) ? ((const float4*)bias)[lane] : make_float4(0.f, 0.f, 0.f, 0.f);
    acc.x += bb.x; acc.y += bb.y; acc.z += bb.z; acc.w += bb.w;

    if (EPI == 0) {
        if (lane < D4) {
            acc.x = fmaxf(acc.x, 0.f); acc.y = fmaxf(acc.y, 0.f);
            acc.z = fmaxf(acc.z, 0.f); acc.w = fmaxf(acc.w, 0.f);
            ((float4*)(xout + (size_t)gw * D))[lane] = acc;
        }
    } else {
        float m = (lane < D4)
                ? fmaxf(fmaxf(acc.x, acc.y), fmaxf(acc.z, acc.w))
                : -INFINITY;
#pragma unroll
        for (int o = 16; o > 0; o >>= 1) m = fmaxf(m, __shfl_xor_sync(0xffffffffu, m, o));
        float s = (lane < D4)
                ? (expf(acc.x - m) + expf(acc.y - m)) + (expf(acc.z - m) + expf(acc.w - m))
                : 0.f;
#pragma unroll
        for (int o = 16; o > 0; o >>= 1) s += __shfl_xor_sync(0xffffffffu, s, o);
        float l = m + logf(s);
        if (lane < D4) {
            acc.x -= l; acc.y -= l; acc.z -= l; acc.w -= l;
            ((float4*)(xout + (size_t)gw * D))[lane] = acc;
        }
    }
}

// ---------------- launch ----------------
extern "C" void kernel_launch(void* const* d_in, const int* in_sizes, int n_in,
                              void* d_out, int out_size) {
    const float* x  = (const float*)d_in[0];
    const float* W1 = (const float*)d_in[1];
    const float* b1 = (const float*)d_in[2];
    const float* W2 = (const float*)d_in[3];
    const float* b2 = (const float*)d_in[4];
    const float* W3 = (const float*)d_in[5];
    const float* b3 = (const float*)d_in[6];
    const int*   ei = (const int*)d_in[7];
    float* out = (float*)d_out;

    __half *p_t1, *p_t2, *p_t3;
    float *p_h1, *p_h2;
    cudaGetSymbolAddress((void**)&p_t1, g_t1);
    cudaGetSymbolAddress((void**)&p_h1, g_h1);
    cudaGetSymbolAddress((void**)&p_t2, g_t2);
    cudaGetSymbolAddress((void**)&p_h2, g_h2);
    cudaGetSymbolAddress((void**)&p_t3, g_t3);

    constexpr int PS1 = F1 + ((8 - (F1 % 32) + 32) % 32);   // 104
    constexpr int PS2 = F2 + ((8 - (F2 % 32) + 32) % 32);   // 104
    constexpr int PS3 = F3 + ((8 - (F3 % 32) + 32) % 32);   // 40
    const int smem1 = 2 * F0 * PS1 * 4;
    const int smem2 = 2 * F1 * PS2 * 4;
    const int smem3 = 2 * F2 * PS3 * 4;

    static cudaStream_t sB = nullptr;
    static cudaEvent_t ev_fork, ev_csr, ev_a1A, ev_g2B, ev_a2A, ev_g3A, ev_g3B, ev_a3B;
    if (!sB) {
        cudaStreamCreateWithFlags(&sB, cudaStreamNonBlocking);
        cudaEventCreateWithFlags(&ev_fork, cudaEventDisableTiming);
        cudaEventCreateWithFlags(&ev_csr,  cudaEventDisableTiming);
        cudaEventCreateWithFlags(&ev_a1A,  cudaEventDisableTiming);
        cudaEventCreateWithFlags(&ev_g2B,  cudaEventDisableTiming);
        cudaEventCreateWithFlags(&ev_a2A,  cudaEventDisableTiming);
        cudaEventCreateWithFlags(&ev_g3A,  cudaEventDisableTiming);
        cudaEventCreateWithFlags(&ev_g3B,  cudaEventDisableTiming);
        cudaEventCreateWithFlags(&ev_a3B,  cudaEventDisableTiming);
        cudaFuncSetAttribute(mma_gemm_kernel<F0, F1>,
                             cudaFuncAttributeMaxDynamicSharedMemorySize, smem1);
        cudaFuncSetAttribute(mma_gemm_kernel<F1, F2>,
                             cudaFuncAttributeMaxDynamicSharedMemorySize, smem2);
        cudaFuncSetAttribute(mma_gemm_kernel<F2, F3>,
                             cudaFuncAttributeMaxDynamicSharedMemorySize, smem3);
    }

    // node-range split
    const int limA = HALF_A;                 // [0, 25152)
    const int cntB = N_NODES - HALF_A;       // [25152, 50000)
    const int gemm_gA = HALF_A / 192;                    // 131
    const int gemm_gB = (cntB + 191) / 192;              // 130
    const int gemm_gF = (N_NODES + 191) / 192;           // 261
    const int agg_gA  = (HALF_A * 32 + 255) / 256;
    const int agg_gB  = (cntB * 32 + 255) / 256;

    // ---- fork: CSR on sB, GEMM1 (full) on main ----
    cudaEventRecord(ev_fork, 0);
    cudaStreamWaitEvent(sB, ev_fork, 0);
    csr_build_kernel<<<NBLK, CSR_THREADS, 0, sB>>>(ei);
    cudaEventRecord(ev_csr, sB);

    mma_gemm_kernel<F0, F1><<<gemm_gF, 192, smem1>>>(x, W1, p_t1, 0, N_NODES);

    // ---- stream A (default): agg1_A -> gemm2_A -> agg2_A -> gemm3_A -> agg3_A ----
    cudaStreamWaitEvent(0, ev_csr, 0);
    agg_kernel<F1, 0><<<agg_gA, 256>>>(p_t1, b1, p_h1, 0, limA);
    cudaEventRecord(ev_a1A, 0);
    mma_gemm_kernel<F1, F2><<<gemm_gA, 192, smem2>>>(p_h1, W2, p_t2, 0, limA);

    // ---- stream B: agg1_B (staggered) -> gemm2_B ----
    cudaStreamWaitEvent(sB, ev_a1A, 0);   // implies t1 complete (gemm1 before a1A on stream A)
    agg_kernel<F1, 0><<<agg_gB, 256, 0, sB>>>(p_t1, b1, p_h1, HALF_A, N_NODES);
    mma_gemm_kernel<F1, F2><<<gemm_gB, 192, smem2, sB>>>(p_h1, W2, p_t2, HALF_A, N_NODES);
    cudaEventRecord(ev_g2B, sB);

    // ---- stream A: agg2_A (needs full t2) -> gemm3_A ----
    cudaStreamWaitEvent(0, ev_g2B, 0);
    agg_kernel<F2, 0><<<agg_gA, 256>>>(p_t2, b2, p_h2, 0, limA);
    cudaEventRecord(ev_a2A, 0);
    mma_gemm_kernel<F2, F3><<<gemm_gA, 192, smem3>>>(p_h2, W3, p_t3, 0, limA);
    cudaEventRecord(ev_g3A, 0);

    // ---- stream B: agg2_B (staggered; a2A implies full t2) -> gemm3_B ----
    cudaStreamWaitEvent(sB, ev_a2A, 0);
    agg_kernel<F2, 0><<<agg_gB, 256, 0, sB>>>(p_t2, b2, p_h2, HALF_A, N_NODES);
    mma_gemm_kernel<F2, F3><<<gemm_gB, 192, smem3, sB>>>(p_h2, W3, p_t3, HALF_A, N_NODES);
    cudaEventRecord(ev_g3B, sB);

    // ---- final aggs (both need full t3), run concurrently ----
    cudaStreamWaitEvent(0, ev_g3B, 0);
    agg_kernel<F3, 1><<<agg_gA, 256>>>(p_t3, b3, out, 0, limA);

    cudaStreamWaitEvent(sB, ev_g3A, 0);
    agg_kernel<F3, 1><<<agg_gB, 256, 0, sB>>>(p_t3, b3, out, HALF_A, N_NODES);
    cudaEventRecord(ev_a3B, sB);

    // join everything back onto the main stream
    cudaStreamWaitEvent(0, ev_a3B, 0);
}

// round 11
// speedup vs baseline: 1.1843x; 1.1843x over previous
#include <cuda_runtime.h>
#include <cuda_fp16.h>
#include <math.h>
#include <stdint.h>

#define N_NODES 50000
#define N_EDGES 800000
#define F0 128
#define F1 96
#define F2 96
#define F3 40
#define NBLK 74
#define CSR_THREADS 1024
#define CHUNK ((N_NODES + NBLK - 1) / NBLK)   // 676

// ---------------- scratch (static device globals; no allocation) ----------------
__device__ int    g_deg[N_NODES];
__device__ int    g_cur[N_NODES];
__device__ int    g_off[N_NODES + 1];
__device__ int    g_csr[N_EDGES];
__device__ int    g_bsum[NBLK];
__device__ int    g_barrier_ctr;
__device__ int    g_done_ctr;
__device__ __half g_t1[(size_t)N_NODES * F1];   // x @ W1       (fp16)
__device__ __half g_h1[(size_t)N_NODES * F1];   // relu(agg+b)  (fp16)
__device__ __half g_t2[(size_t)N_NODES * F2];   // h1 @ W2      (fp16)
__device__ __half g_h2[(size_t)N_NODES * F2];   // relu(agg+b)  (fp16)
__device__ __half g_t3[(size_t)N_NODES * F3];   // h2 @ W3      (fp16)

// ---------------- edge index access ----------------
__device__ __forceinline__ int edge_src(const int* ei, int e, int is64) {
    return is64 ? ei[2 * e] : ei[e];
}
__device__ __forceinline__ int edge_dst(const int* ei, int e, int is64) {
    return is64 ? ei[2 * (N_EDGES + e)] : ei[N_EDGES + e];
}

// ---------------- software grid barrier (74 co-resident blocks) ----------------
__device__ __forceinline__ void grid_barrier(int phase) {
    __syncthreads();
    if (threadIdx.x == 0) {
        __threadfence();
        atomicAdd(&g_barrier_ctr, 1);
        int target = phase * NBLK;
        while ((*(volatile int*)&g_barrier_ctr) - target < 0)
            __nanosleep(64);
    }
    __syncthreads();
    __threadfence();
}

// ---------------- single persistent CSR-build kernel ----------------
__global__ void __launch_bounds__(CSR_THREADS) csr_build_kernel(const int* __restrict__ ei) {
    __shared__ int s_is64;
    __shared__ int s_boff;
    __shared__ int wsum[32];

    int tid  = threadIdx.x;
    int lane = tid & 31, w = tid >> 5;
    int gtid = blockIdx.x * CSR_THREADS + tid;
    constexpr int NT = NBLK * CSR_THREADS;

    if (tid < 32) {
        int acc = 0;
#pragma unroll
        for (int j = 0; j < 4; j++) acc |= ei[1 + 2 * (tid * 4 + j)];
#pragma unroll
        for (int o = 16; o > 0; o >>= 1) acc |= __shfl_xor_sync(0xffffffffu, acc, o);
        if (tid == 0) s_is64 = (acc == 0) ? 1 : 0;
    }
    __syncthreads();
    int is64 = s_is64;

    for (int i = gtid; i < N_NODES; i += NT) g_deg[i] = 0;
    grid_barrier(1);

    for (int e = gtid; e < N_EDGES; e += NT)
        atomicAdd(&g_deg[edge_dst(ei, e, is64)], 1);
    grid_barrier(2);

    int cbase = blockIdx.x * CHUNK;
    int i0 = cbase + tid;
    int v = (tid < CHUNK && i0 < N_NODES) ? g_deg[i0] : 0;
    {
        int s = v;
#pragma unroll
        for (int o = 16; o > 0; o >>= 1) s += __shfl_xor_sync(0xffffffffu, s, o);
        if (lane == 0) wsum[w] = s;
        __syncthreads();
        if (w == 0) {
            int t = wsum[lane];
#pragma unroll
            for (int o = 16; o > 0; o >>= 1) t += __shfl_xor_sync(0xffffffffu, t, o);
            if (lane == 0) g_bsum[blockIdx.x] = t;
        }
    }
    grid_barrier(3);

    if (tid == 0) {
        int s = 0;
        for (int b = 0; b < (int)blockIdx.x; b++) s += g_bsum[b];
        s_boff = s;
    }
    __syncthreads();
    {
        int incl = v;
#pragma unroll
        for (int o = 1; o < 32; o <<= 1) {
            int u = __shfl_up_sync(0xffffffffu, incl, o);
            if (lane >= o) incl += u;
        }
        if (lane == 31) wsum[w] = incl;
        __syncthreads();
        if (w == 0) {
            int s = wsum[lane];
#pragma unroll
            for (int o = 1; o < 32; o <<= 1) {
                int u = __shfl_up_sync(0xffffffffu, s, o);
                if (lane >= o) s += u;
            }
            wsum[lane] = s;
        }
        __syncthreads();
        incl += ((w > 0) ? wsum[w - 1] : 0) + s_boff;
        if (tid < CHUNK && i0 < N_NODES) {
            g_off[i0 + 1] = incl;
            g_cur[i0]     = incl - v;
        }
        if (blockIdx.x == 0 && tid == 0) g_off[0] = 0;
    }
    grid_barrier(4);

    for (int e = gtid; e < N_EDGES; e += NT) {
        int d = edge_dst(ei, e, is64);
        int s = edge_src(ei, e, is64);
        int p = atomicAdd(&g_cur[d], 1);
        g_csr[p] = s;
    }

    __syncthreads();
    if (tid == 0) {
        __threadfence();
        int d = atomicAdd(&g_done_ctr, 1);
        if (d == NBLK - 1) {
            g_barrier_ctr = 0;
            g_done_ctr = 0;
            __threadfence();
        }
    }
}

// ---------------- MMA helpers ----------------
__device__ __forceinline__ uint32_t f2tf32(float f) {
    uint32_t r;
    asm("cvt.rna.tf32.f32 %0, %1;" : "=r"(r) : "f"(f));
    return r;
}

__device__ __forceinline__ void mma8_tf32(float c[4], const uint32_t a[4],
                                          uint32_t b0, uint32_t b1) {
    asm volatile(
        "mma.sync.aligned.m16n8k8.row.col.f32.tf32.tf32.f32 "
        "{%0,%1,%2,%3}, {%4,%5,%6,%7}, {%8,%9}, {%0,%1,%2,%3};"
        : "+f"(c[0]), "+f"(c[1]), "+f"(c[2]), "+f"(c[3])
        : "r"(a[0]), "r"(a[1]), "r"(a[2]), "r"(a[3]), "r"(b0), "r"(b1));
}

__device__ __forceinline__ void mma16_f16(float c[4],
                                          uint32_t a0, uint32_t a1, uint32_t a2, uint32_t a3,
                                          uint32_t b0, uint32_t b1) {
    asm volatile(
        "mma.sync.aligned.m16n8k16.row.col.f32.f16.f16.f32 "
        "{%0,%1,%2,%3}, {%4,%5,%6,%7}, {%8,%9}, {%0,%1,%2,%3};"
        : "+f"(c[0]), "+f"(c[1]), "+f"(c[2]), "+f"(c[3])
        : "r"(a0), "r"(a1), "r"(a2), "r"(a3), "r"(b0), "r"(b1));
}

// ---------------- GEMM1: 3xTF32, fp32 X -> fp16 Y (overlapped with CSR) ----------------
template <int K, int N>
__global__ void __launch_bounds__(192, 2) mma_gemm_kernel(
        const float* __restrict__ X, const float* __restrict__ W,
        __half* __restrict__ Y) {
    constexpr int NT  = N / 8;
    constexpr int PAD = (8 - (N % 32) + 32) % 32;
    constexpr int PS  = N + PAD;
    extern __shared__ uint32_t smem[];
    uint32_t* sHi = smem;
    uint32_t* sLo = smem + K * PS;

    int tid = threadIdx.x;
    for (int i = tid; i < K * N; i += 192) {
        int k = i / N, n = i % N;
        float w = __ldg(W + i);
        uint32_t hi = f2tf32(w);
        sHi[k * PS + n] = hi;
        sLo[k * PS + n] = f2tf32(w - __uint_as_float(hi));
    }
    __syncthreads();

    int warp = tid >> 5, lane = tid & 31;
    int tig = lane & 3, grp = lane >> 2;
    int row0 = blockIdx.x * 192 + warp * 32;
    int r0 = row0 + grp,      r1 = row0 + grp + 8;
    int r2 = row0 + grp + 16, r3 = row0 + grp + 24;
    const float* xr0 = X + (size_t)((r0 < N_NODES) ? r0 : (N_NODES - 1)) * K;
    const float* xr1 = X + (size_t)((r1 < N_NODES) ? r1 : (N_NODES - 1)) * K;
    const float* xr2 = X + (size_t)((r2 < N_NODES) ? r2 : (N_NODES - 1)) * K;
    const float* xr3 = X + (size_t)((r3 < N_NODES) ? r3 : (N_NODES - 1)) * K;

    float c0[NT][4], c1[NT][4];
#pragma unroll
    for (int nt = 0; nt < NT; nt++)
#pragma unroll
        for (int j = 0; j < 4; j++) { c0[nt][j] = 0.f; c1[nt][j] = 0.f; }

#pragma unroll 1
    for (int k0 = 0; k0 < K; k0 += 8) {
        float a0 = __ldg(xr0 + k0 + tig);
        float a1 = __ldg(xr1 + k0 + tig);
        float a2 = __ldg(xr0 + k0 + tig + 4);
        float a3 = __ldg(xr1 + k0 + tig + 4);
        float a4 = __ldg(xr2 + k0 + tig);
        float a5 = __ldg(xr3 + k0 + tig);
        float a6 = __ldg(xr2 + k0 + tig + 4);
        float a7 = __ldg(xr3 + k0 + tig + 4);
        uint32_t ahi0[4] = {f2tf32(a0), f2tf32(a1), f2tf32(a2), f2tf32(a3)};
        uint32_t alo0[4] = {f2tf32(a0 - __uint_as_float(ahi0[0])),
                            f2tf32(a1 - __uint_as_float(ahi0[1])),
                            f2tf32(a2 - __uint_as_float(ahi0[2])),
                            f2tf32(a3 - __uint_as_float(ahi0[3]))};
        uint32_t ahi1[4] = {f2tf32(a4), f2tf32(a5), f2tf32(a6), f2tf32(a7)};
        uint32_t alo1[4] = {f2tf32(a4 - __uint_as_float(ahi1[0])),
                            f2tf32(a5 - __uint_as_float(ahi1[1])),
                            f2tf32(a6 - __uint_as_float(ahi1[2])),
                            f2tf32(a7 - __uint_as_float(ahi1[3]))};
        const uint32_t* rHi0 = sHi + (k0 + tig) * PS + grp;
        const uint32_t* rHi1 = sHi + (k0 + tig + 4) * PS + grp;
        const uint32_t* rLo0 = sLo + (k0 + tig) * PS + grp;
        const uint32_t* rLo1 = sLo + (k0 + tig + 4) * PS + grp;
#pragma unroll
        for (int nt = 0; nt < NT; nt++) {
            uint32_t b0h = rHi0[nt * 8], b1h = rHi1[nt * 8];
            uint32_t b0l = rLo0[nt * 8], b1l = rLo1[nt * 8];
            mma8_tf32(c0[nt], ahi0, b0h, b1h);
            mma8_tf32(c0[nt], alo0, b0h, b1h);
            mma8_tf32(c0[nt], ahi0, b0l, b1l);
            mma8_tf32(c1[nt], ahi1, b0h, b1h);
            mma8_tf32(c1[nt], alo1, b0h, b1h);
            mma8_tf32(c1[nt], ahi1, b0l, b1l);
        }
    }

#pragma unroll
    for (int nt = 0; nt < NT; nt++) {
        int col = nt * 8 + 2 * tig;
        if (r0 < N_NODES)
            *(__half2*)(Y + (size_t)r0 * N + col) = __floats2half2_rn(c0[nt][0], c0[nt][1]);
        if (r1 < N_NODES)
            *(__half2*)(Y + (size_t)r1 * N + col) = __floats2half2_rn(c0[nt][2], c0[nt][3]);
        if (r2 < N_NODES)
            *(__half2*)(Y + (size_t)r2 * N + col) = __floats2half2_rn(c1[nt][0], c1[nt][1]);
        if (r3 < N_NODES)
            *(__half2*)(Y + (size_t)r3 * N + col) = __floats2half2_rn(c1[nt][2], c1[nt][3]);
    }
}

// ---------------- GEMM2/3: fp16 m16n8k16, W = hi+lo fp16 (2 passes) ----------------
// A direct from fp16 memory; B pairs (k,k+1) packed half2 in smem, PS in 4B units = 8 mod 32.
template <int K, int N>
__global__ void __launch_bounds__(192, 2) mma_gemm_h_kernel(
        const __half* __restrict__ X, const float* __restrict__ W,
        __half* __restrict__ Y) {
    constexpr int NT  = N / 8;
    constexpr int KP  = K / 2;                    // k-pairs
    constexpr int PAD = (8 - (N % 32) + 32) % 32;
    constexpr int PS  = N + PAD;                  // half2 elements per pair-row
    extern __shared__ uint32_t smem[];
    uint32_t* sHi = smem;                         // half2(W[2kp][n], W[2kp+1][n]) hi
    uint32_t* sLo = smem + KP * PS;               // residual lo

    int tid = threadIdx.x;
    for (int i = tid; i < KP * N; i += 192) {
        int kp = i / N, n = i % N;
        float w0 = __ldg(W + (2 * kp) * N + n);
        float w1 = __ldg(W + (2 * kp + 1) * N + n);
        __half h0 = __float2half_rn(w0), h1 = __float2half_rn(w1);
        __half l0 = __float2half_rn(w0 - __half2float(h0));
        __half l1 = __float2half_rn(w1 - __half2float(h1));
        __half2 hh = __halves2half2(h0, h1), ll = __halves2half2(l0, l1);
        sHi[kp * PS + n] = *reinterpret_cast<uint32_t*>(&hh);
        sLo[kp * PS + n] = *reinterpret_cast<uint32_t*>(&ll);
    }
    __syncthreads();

    int warp = tid >> 5, lane = tid & 31;
    int tig = lane & 3, grp = lane >> 2;
    int row0 = blockIdx.x * 192 + warp * 32;
    int r0 = row0 + grp,      r1 = row0 + grp + 8;
    int r2 = row0 + grp + 16, r3 = row0 + grp + 24;
    const __half* xr0 = X + (size_t)((r0 < N_NODES) ? r0 : (N_NODES - 1)) * K;
    const __half* xr1 = X + (size_t)((r1 < N_NODES) ? r1 : (N_NODES - 1)) * K;
    const __half* xr2 = X + (size_t)((r2 < N_NODES) ? r2 : (N_NODES - 1)) * K;
    const __half* xr3 = X + (size_t)((r3 < N_NODES) ? r3 : (N_NODES - 1)) * K;

    float c0[NT][4], c1[NT][4];
#pragma unroll
    for (int nt = 0; nt < NT; nt++)
#pragma unroll
        for (int j = 0; j < 4; j++) { c0[nt][j] = 0.f; c1[nt][j] = 0.f; }

#pragma unroll 1
    for (int k0 = 0; k0 < K; k0 += 16) {
        // A fragments: rows (grp, grp+8) tile0 / (grp+16, grp+24) tile1,
        // cols (2tig, 2tig+1) and (2tig+8, 2tig+9) as aligned half2 loads
        uint32_t a00 = __ldg((const uint32_t*)(xr0 + k0 + 2 * tig));
        uint32_t a01 = __ldg((const uint32_t*)(xr1 + k0 + 2 * tig));
        uint32_t a02 = __ldg((const uint32_t*)(xr0 + k0 + 2 * tig + 8));
        uint32_t a03 = __ldg((const uint32_t*)(xr1 + k0 + 2 * tig + 8));
        uint32_t a10 = __ldg((const uint32_t*)(xr2 + k0 + 2 * tig));
        uint32_t a11 = __ldg((const uint32_t*)(xr3 + k0 + 2 * tig));
        uint32_t a12 = __ldg((const uint32_t*)(xr2 + k0 + 2 * tig + 8));
        uint32_t a13 = __ldg((const uint32_t*)(xr3 + k0 + 2 * tig + 8));

        int kp0 = (k0 >> 1) + tig;        // pair row for b0
        int kp1 = kp0 + 4;                // pair row for b1
        const uint32_t* rHi0 = sHi + kp0 * PS + grp;
        const uint32_t* rHi1 = sHi + kp1 * PS + grp;
        const uint32_t* rLo0 = sLo + kp0 * PS + grp;
        const uint32_t* rLo1 = sLo + kp1 * PS + grp;
#pragma unroll
        for (int nt = 0; nt < NT; nt++) {
            uint32_t b0h = rHi0[nt * 8], b1h = rHi1[nt * 8];
            uint32_t b0l = rLo0[nt * 8], b1l = rLo1[nt * 8];
            mma16_f16(c0[nt], a00, a01, a02, a03, b0h, b1h);
            mma16_f16(c0[nt], a00, a01, a02, a03, b0l, b1l);
            mma16_f16(c1[nt], a10, a11, a12, a13, b0h, b1h);
            mma16_f16(c1[nt], a10, a11, a12, a13, b0l, b1l);
        }
    }

#pragma unroll
    for (int nt = 0; nt < NT; nt++) {
        int col = nt * 8 + 2 * tig;
        if (r0 < N_NODES)
            *(__half2*)(Y + (size_t)r0 * N + col) = __floats2half2_rn(c0[nt][0], c0[nt][1]);
        if (r1 < N_NODES)
            *(__half2*)(Y + (size_t)r1 * N + col) = __floats2half2_rn(c0[nt][2], c0[nt][3]);
        if (r2 < N_NODES)
            *(__half2*)(Y + (size_t)r2 * N + col) = __floats2half2_rn(c1[nt][0], c1[nt][1]);
        if (r3 < N_NODES)
            *(__half2*)(Y + (size_t)r3 * N + col) = __floats2half2_rn(c1[nt][2], c1[nt][3]);
    }
}

// ---------------- gather aggregation (fp16 in, fp32 accum) + fused epilogue ----------------
__device__ __forceinline__ void acc_h4(float4& acc, uint2 v) {
    float2 f0 = __half22float2(*reinterpret_cast<__half2*>(&v.x));
    float2 f1 = __half22float2(*reinterpret_cast<__half2*>(&v.y));
    acc.x += f0.x; acc.y += f0.y; acc.z += f1.x; acc.w += f1.y;
}

// EPI 0: relu(acc+bias) -> fp16   EPI 1: log_softmax(acc+bias) -> fp32
template <int D, int EPI>
__global__ void agg_kernel(const __half* __restrict__ xin, const float* __restrict__ bias,
                           void* __restrict__ xout) {
    int gw   = (blockIdx.x * blockDim.x + threadIdx.x) >> 5;
    int lane = threadIdx.x & 31;
    if (gw >= N_NODES) return;
    constexpr int D4 = D / 4;
    float4 acc = make_float4(0.f, 0.f, 0.f, 0.f);
    int beg = g_off[gw], end = g_off[gw + 1];
    int e = beg;
    for (; e + 3 < end; e += 4) {
        int s0 = g_csr[e], s1 = g_csr[e + 1], s2 = g_csr[e + 2], s3 = g_csr[e + 3];
        if (lane < D4) {
            uint2 v0 = __ldg((const uint2*)(xin + (size_t)s0 * D) + lane);
            uint2 v1 = __ldg((const uint2*)(xin + (size_t)s1 * D) + lane);
            uint2 v2 = __ldg((const uint2*)(xin + (size_t)s2 * D) + lane);
            uint2 v3 = __ldg((const uint2*)(xin + (size_t)s3 * D) + lane);
            acc_h4(acc, v0);
            acc_h4(acc, v1);
            acc_h4(acc, v2);
            acc_h4(acc, v3);
        }
    }
    for (; e < end; e++) {
        int s0 = g_csr[e];
        if (lane < D4) {
            uint2 v = __ldg((const uint2*)(xin + (size_t)s0 * D) + lane);
            acc_h4(acc, v);
        }
    }
    float4 bb = (lane < D4) ? ((const float4*)bias)[lane] : make_float4(0.f, 0.f, 0.f, 0.f);
    acc.x += bb.x; acc.y += bb.y; acc.z += bb.z; acc.w += bb.w;

    if (EPI == 0) {
        if (lane < D4) {
            __half2 o0 = __floats2half2_rn(fmaxf(acc.x, 0.f), fmaxf(acc.y, 0.f));
            __half2 o1 = __floats2half2_rn(fmaxf(acc.z, 0.f), fmaxf(acc.w, 0.f));
            uint2 pack;
            pack.x = *reinterpret_cast<uint32_t*>(&o0);
            pack.y = *reinterpret_cast<uint32_t*>(&o1);
            ((uint2*)((__half*)xout + (size_t)gw * D))[lane] = pack;
        }
    } else {
        float m = (lane < D4)
                ? fmaxf(fmaxf(acc.x, acc.y), fmaxf(acc.z, acc.w))
                : -INFINITY;
#pragma unroll
        for (int o = 16; o > 0; o >>= 1) m = fmaxf(m, __shfl_xor_sync(0xffffffffu, m, o));
        float s = (lane < D4)
                ? (expf(acc.x - m) + expf(acc.y - m)) + (expf(acc.z - m) + expf(acc.w - m))
                : 0.f;
#pragma unroll
        for (int o = 16; o > 0; o >>= 1) s += __shfl_xor_sync(0xffffffffu, s, o);
        float l = m + logf(s);
        if (lane < D4) {
            acc.x -= l; acc.y -= l; acc.z -= l; acc.w -= l;
            ((float4*)((float*)xout + (size_t)gw * D))[lane] = acc;
        }
    }
}

// ---------------- launch ----------------
extern "C" void kernel_launch(void* const* d_in, const int* in_sizes, int n_in,
                              void* d_out, int out_size) {
    const float* x  = (const float*)d_in[0];
    const float* W1 = (const float*)d_in[1];
    const float* b1 = (const float*)d_in[2];
    const float* W2 = (const float*)d_in[3];
    const float* b2 = (const float*)d_in[4];
    const float* W3 = (const float*)d_in[5];
    const float* b3 = (const float*)d_in[6];
    const int*   ei = (const int*)d_in[7];
    float* out = (float*)d_out;

    __half *p_t1, *p_h1, *p_t2, *p_h2, *p_t3;
    cudaGetSymbolAddress((void**)&p_t1, g_t1);
    cudaGetSymbolAddress((void**)&p_h1, g_h1);
    cudaGetSymbolAddress((void**)&p_t2, g_t2);
    cudaGetSymbolAddress((void**)&p_h2, g_h2);
    cudaGetSymbolAddress((void**)&p_t3, g_t3);

    constexpr int PS1 = F1 + ((8 - (F1 % 32) + 32) % 32);   // 104
    constexpr int PS2 = F2 + ((8 - (F2 % 32) + 32) % 32);   // 104
    constexpr int PS3 = F3 + ((8 - (F3 % 32) + 32) % 32);   // 40
    const int smem1 = 2 * F0 * PS1 * 4;            // tf32 hi+lo (uint32)
    const int smem2 = 2 * (F1 / 2) * PS2 * 4;      // fp16 pairs hi+lo (uint32)
    const int smem3 = 2 * (F2 / 2) * PS3 * 4;

    static cudaStream_t sB = nullptr;
    static cudaEvent_t ev_fork = nullptr, ev_join = nullptr;
    if (!sB) {
        cudaStreamCreateWithFlags(&sB, cudaStreamNonBlocking);
        cudaEventCreateWithFlags(&ev_fork, cudaEventDisableTiming);
        cudaEventCreateWithFlags(&ev_join, cudaEventDisableTiming);
        cudaFuncSetAttribute(mma_gemm_kernel<F0, F1>,
                             cudaFuncAttributeMaxDynamicSharedMemorySize, smem1);
        cudaFuncSetAttribute(mma_gemm_h_kernel<F1, F2>,
                             cudaFuncAttributeMaxDynamicSharedMemorySize, smem2);
        cudaFuncSetAttribute(mma_gemm_h_kernel<F2, F3>,
                             cudaFuncAttributeMaxDynamicSharedMemorySize, smem3);
    }

    // fork: persistent CSR build on sB, GEMM1 on main stream
    cudaEventRecord(ev_fork, 0);
    cudaStreamWaitEvent(sB, ev_fork, 0);
    csr_build_kernel<<<NBLK, CSR_THREADS, 0, sB>>>(ei);
    cudaEventRecord(ev_join, sB);

    const int agg_grid  = (N_NODES * 32 + 255) / 256;
    const int gemm_grid = (N_NODES + 191) / 192;   // 261 blocks

    // main stream: t1 = x @ W1 (independent of CSR)
    mma_gemm_kernel<F0, F1><<<gemm_grid, 192, smem1>>>(x, W1, p_t1);

    // join: aggregation needs CSR
    cudaStreamWaitEvent(0, ev_join, 0);

    // layer 1: h1 = relu(agg(t1) + b1)  (fp16)
    agg_kernel<F1, 0><<<agg_grid, 256>>>(p_t1, b1, p_h1);
    // layer 2 (fp16 MMA)
    mma_gemm_h_kernel<F1, F2><<<gemm_grid, 192, smem2>>>(p_h1, W2, p_t2);
    agg_kernel<F2, 0><<<agg_grid, 256>>>(p_t2, b2, p_h2);
    // layer 3 (fp16 MMA) + log_softmax
    mma_gemm_h_kernel<F2, F3><<<gemm_grid, 192, smem3>>>(p_h2, W3, p_t3);
    agg_kernel<F3, 1><<<agg_grid, 256>>>(p_t3, b3, out);
}